// round 4
// baseline (speedup 1.0000x reference)
#include <cuda_runtime.h>

#define Bb 8
#define Ss 1024
#define Dd 768
#define Hh 12
#define HDd 64

// ---------------- device scratch (no allocations allowed) ----------------
__device__ float g_Q[(size_t)Bb * Hh * Ss * HDd];   // [B,H,S,HD]
__device__ float g_K[(size_t)Bb * Hh * Ss * HDd];
__device__ float g_V[(size_t)Bb * Hh * Ss * HDd];
__device__ float g_rel[(size_t)Bb * Ss * Ss];       // rel_attn (head-independent)
__device__ unsigned char g_mask[(size_t)Bb * Ss * Ss];
__device__ int g_mmode;

// ---------------- mask dtype detection (bool/u8 vs int32 vs float32) -----
__global__ void mask_detect_kernel(const void* mp) {
    __shared__ int allf, alli;
    if (threadIdx.x == 0) { allf = 1; alli = 1; }
    __syncthreads();
    const float* f = (const float*)mp;
    const int* w = (const int*)mp;
    float v = f[threadIdx.x];
    int iv = w[threadIdx.x];
    if (!(v == 0.0f || v == 1.0f)) allf = 0;
    if (!(iv == 0 || iv == 1)) alli = 0;
    __syncthreads();
    if (threadIdx.x == 0) g_mmode = allf ? 0 : (alli ? 1 : 2);
}

__global__ void mask_convert_kernel(const void* mp) {
    size_t i = (size_t)blockIdx.x * blockDim.x + threadIdx.x;
    int mode = g_mmode;
    unsigned char m;
    if (mode == 0)      m = (((const float*)mp)[i] != 0.0f);
    else if (mode == 1) m = (((const int*)mp)[i] != 0);
    else                m = (((const unsigned char*)mp)[i] != 0);
    g_mask[i] = m;
}

// ---------------- rel_attn softmax: one row (b,q) per block --------------
__global__ void rel_softmax_kernel(const float* __restrict__ rel) {
    int row = blockIdx.x;                       // b*S + q
    const float* r = rel + (size_t)row * Ss;
    const unsigned char* m = g_mask + (size_t)row * Ss;
    int tid = threadIdx.x;
    int w = tid >> 5, l = tid & 31;

    float v[4];
    float mx = -1e30f;
#pragma unroll
    for (int j = 0; j < 4; j++) {
        int i = tid + j * 256;
        float relm = m[i] ? r[i] : 0.0f;        // == rel * mask_float exactly
        v[j] = (relm == 0.0f) ? -10000.0f : relm;
        mx = fmaxf(mx, v[j]);
    }
    __shared__ float red[8];
#pragma unroll
    for (int o = 16; o; o >>= 1) mx = fmaxf(mx, __shfl_xor_sync(0xffffffffu, mx, o));
    if (l == 0) red[w] = mx;
    __syncthreads();
    if (w == 0) {
        float t = (l < 8) ? red[l] : -1e30f;
#pragma unroll
        for (int o = 4; o; o >>= 1) t = fmaxf(t, __shfl_xor_sync(0xffffffffu, t, o));
        if (l == 0) red[0] = t;
    }
    __syncthreads();
    mx = red[0];
    __syncthreads();

    float e[4], sum = 0.0f;
#pragma unroll
    for (int j = 0; j < 4; j++) { e[j] = expf(v[j] - mx); sum += e[j]; }
#pragma unroll
    for (int o = 16; o; o >>= 1) sum += __shfl_xor_sync(0xffffffffu, sum, o);
    if (l == 0) red[w] = sum;
    __syncthreads();
    if (w == 0) {
        float t = (l < 8) ? red[l] : 0.0f;
#pragma unroll
        for (int o = 4; o; o >>= 1) t += __shfl_xor_sync(0xffffffffu, t, o);
        if (l == 0) red[0] = t;
    }
    __syncthreads();
    float inv = 1.0f / red[0];
#pragma unroll
    for (int j = 0; j < 4; j++)
        g_rel[(size_t)row * Ss + tid + j * 256] = e[j] * inv;
}

// ---------------- fused 3-way projection GEMM ----------------------------
// C[i,j] = sum_k X[i,k] * W[j,k] + bias[j], written into [B,H,S,HD] scratch.
__global__ void proj_kernel(const float* __restrict__ Xq, const float* __restrict__ Xk, const float* __restrict__ Xv,
                            const float* __restrict__ Wq, const float* __restrict__ Wk, const float* __restrict__ Wv,
                            const float* __restrict__ bqp, const float* __restrict__ bkp, const float* __restrict__ bvp) {
    int z = blockIdx.z;
    const float* X = (z == 0) ? Xq : (z == 1) ? Xk : Xv;
    const float* W = (z == 0) ? Wq : (z == 1) ? Wk : Wv;
    const float* bias = (z == 0) ? bqp : (z == 1) ? bkp : bvp;
    float* Out = (z == 0) ? g_Q : (z == 1) ? g_K : g_V;

    __shared__ float As[16][128];
    __shared__ float Bs[16][128];
    int i0 = blockIdx.y * 128, j0 = blockIdx.x * 128;
    int tid = threadIdx.x, tx = tid & 15, ty = tid >> 4;
    float acc[8][8];
#pragma unroll
    for (int a = 0; a < 8; a++)
#pragma unroll
        for (int c = 0; c < 8; c++) acc[a][c] = 0.0f;

    int lr = tid >> 2;          // 0..63
    int lc = (tid & 3) * 4;     // 0,4,8,12

    for (int k0 = 0; k0 < Dd; k0 += 16) {
#pragma unroll
        for (int p = 0; p < 2; p++) {
            int row = lr + p * 64;
            float4 a = *(const float4*)(X + (size_t)(i0 + row) * Dd + k0 + lc);
            As[lc + 0][row] = a.x; As[lc + 1][row] = a.y; As[lc + 2][row] = a.z; As[lc + 3][row] = a.w;
            float4 w4 = *(const float4*)(W + (size_t)(j0 + row) * Dd + k0 + lc);
            Bs[lc + 0][row] = w4.x; Bs[lc + 1][row] = w4.y; Bs[lc + 2][row] = w4.z; Bs[lc + 3][row] = w4.w;
        }
        __syncthreads();
#pragma unroll
        for (int kk = 0; kk < 16; kk++) {
            float a[8], bb[8];
#pragma unroll
            for (int u = 0; u < 8; u++) a[u] = As[kk][ty * 8 + u];
#pragma unroll
            for (int u = 0; u < 8; u++) bb[u] = Bs[kk][tx * 8 + u];
#pragma unroll
            for (int ii = 0; ii < 8; ii++)
#pragma unroll
                for (int jj = 0; jj < 8; jj++) acc[ii][jj] += a[ii] * bb[jj];
        }
        __syncthreads();
    }
#pragma unroll
    for (int ii = 0; ii < 8; ii++) {
        int i = i0 + ty * 8 + ii;
        int bI = i >> 10, s = i & 1023;
#pragma unroll
        for (int jj = 0; jj < 8; jj++) {
            int j = j0 + tx * 8 + jj;
            int hI = j >> 6, hd = j & 63;
            Out[(((size_t)bI * Hh + hI) * Ss + s) * HDd + hd] = acc[ii][jj] + bias[j];
        }
    }
}

// ---------------- fused attention ---------------------------------------
// One block per (b, h, 32 q-rows). 512 threads.
// Phase1: S_tile = Q @ K^T /8, mask -> SMEM (32x1024 fp32)
// Phase2: row softmax + mix with rel_attn, write prob_attn
// Phase3: out = P @ V
#define QT 32
#define KT 128
#define SS_FLOATS (QT * Ss)        // 32768
#define SQ_FLOATS (QT * HDd)       // 2048
#define KV_FLOATS 8704             // max(64*132, 128*68)
#define ATTN_SMEM ((SS_FLOATS + SQ_FLOATS + KV_FLOATS) * 4)

__global__ void __launch_bounds__(512, 1)
attn_kernel(const float* __restrict__ l1p, float* __restrict__ outp, float* __restrict__ probp) {
    extern __shared__ float sm[];
    float* sS = sm;                  // [QT][1024] scores/probs
    float* sQ = sS + SS_FLOATS;      // [QT][64]
    float* sT = sQ + SQ_FLOATS;      // K tile: [64 dims][132] transposed ; V tile: [128 rows][68]

    int qt = blockIdx.x * QT;
    int h = blockIdx.y, b = blockIdx.z;
    int tid = threadIdx.x;
    int tx = tid & 15;               // k-group / hd-group
    int ty = tid >> 4;               // q row (0..31)
    const size_t bh = (size_t)b * Hh + h;
    const float* Qg = g_Q + (bh * Ss + qt) * HDd;
    const float* Kg = g_K + bh * Ss * HDd;
    const float* Vg = g_V + bh * Ss * HDd;

    for (int t = tid; t < QT * HDd; t += 512) sQ[t] = Qg[t];
    float l1 = *l1p, l0 = 1.0f - l1;

    // ---------------- phase 1: scores ----------------
    int kb = tx * 8;
    int q = ty;
    for (int kt = 0; kt < Ss; kt += KT) {
        __syncthreads();   // protect sT reuse + first-iter sQ visibility
        for (int t = tid; t < KT * HDd; t += 512) {
            int r = t >> 6, c = t & 63;
            sT[c * 132 + r] = Kg[(size_t)(kt + r) * HDd + c];   // [dim][krow]
        }
        __syncthreads();
        float r0[8];
#pragma unroll
        for (int u = 0; u < 8; u++) r0[u] = 0.0f;
        for (int kk = 0; kk < HDd; kk++) {
            float a0 = sQ[q * HDd + kk];
            float bv[8];
            *(float4*)(bv)     = *(const float4*)(sT + kk * 132 + kb);
            *(float4*)(bv + 4) = *(const float4*)(sT + kk * 132 + kb + 4);
#pragma unroll
            for (int u = 0; u < 8; u++) r0[u] += a0 * bv[u];
        }
        const unsigned char* m0 = g_mask + ((size_t)b * Ss + qt + q) * Ss + kt + kb;
#pragma unroll
        for (int u = 0; u < 8; u++) {
            float v0 = r0[u] * 0.125f;              // 1/sqrt(64)
            if (m0[u]) v0 = -1000000000.0f;
            sS[q * Ss + kt + kb + u] = v0;
        }
    }
    __syncthreads();

    // ---------------- phase 2: softmax + mix + prob write ----------------
    int wid = tid >> 5, lane = tid & 31;
    for (int rq = wid * 2; rq < wid * 2 + 2; rq++) {
        float* row = sS + rq * Ss;
        float mx = -1e30f;
        for (int i = lane; i < Ss; i += 32) mx = fmaxf(mx, row[i]);
#pragma unroll
        for (int o = 16; o; o >>= 1) mx = fmaxf(mx, __shfl_xor_sync(0xffffffffu, mx, o));
        float sum = 0.0f;
        for (int i = lane; i < Ss; i += 32) { float e = expf(row[i] - mx); row[i] = e; sum += e; }
#pragma unroll
        for (int o = 16; o; o >>= 1) sum += __shfl_xor_sync(0xffffffffu, sum, o);
        float inv = 1.0f / sum;
        const float* ra = g_rel + ((size_t)b * Ss + qt + rq) * Ss;
        float* pg = probp + (bh * Ss + qt + rq) * Ss;
        for (int i = lane; i < Ss; i += 32) {
            float p = l0 * row[i] * inv + l1 * ra[i];
            row[i] = p;
            pg[i] = p;
        }
    }
    __syncthreads();

    // ---------------- phase 3: out = P @ V ----------------
    int hd0 = tx * 4;
    float o0[4] = {0.0f, 0.0f, 0.0f, 0.0f};
    for (int kt = 0; kt < Ss; kt += KT) {
        for (int t = tid; t < KT * HDd; t += 512) {
            int r = t >> 6, c = t & 63;
            sT[r * 68 + c] = Vg[(size_t)(kt + r) * HDd + c];    // [krow][dim]
        }
        __syncthreads();
        for (int kk = 0; kk < KT; kk++) {
            float p0 = sS[q * Ss + kt + kk];
            float vv[4];
            *(float4*)vv = *(const float4*)(sT + kk * 68 + hd0);
#pragma unroll
            for (int u = 0; u < 4; u++) o0[u] += p0 * vv[u];
        }
        __syncthreads();
    }
    float* og = outp + ((size_t)b * Ss + qt + q) * Dd + h * HDd + hd0;
#pragma unroll
    for (int u = 0; u < 4; u++) og[u] = o0[u];
}

// ---------------- launcher ----------------------------------------------
extern "C" void kernel_launch(void* const* d_in, const int* in_sizes, int n_in,
                              void* d_out, int out_size) {
    const float* q   = (const float*)d_in[0];
    const float* k   = (const float*)d_in[1];
    const float* v   = (const float*)d_in[2];
    const float* rel = (const float*)d_in[3];
    const void*  msk = d_in[4];
    const float* l1  = (const float*)d_in[5];
    const float* Wq  = (const float*)d_in[6];
    const float* bq  = (const float*)d_in[7];
    const float* Wk  = (const float*)d_in[8];
    const float* bk  = (const float*)d_in[9];
    const float* Wv  = (const float*)d_in[10];
    const float* bv  = (const float*)d_in[11];

    float* outp = (float*)d_out;
    float* probp = outp + (size_t)Bb * Ss * Dd;   // [out | prob_attn]

    mask_detect_kernel<<<1, 256>>>(msk);
    mask_convert_kernel<<<(Bb * Ss * Ss) / 256, 256>>>(msk);
    rel_softmax_kernel<<<Bb * Ss, 256>>>(rel);

    dim3 gp(Dd / 128, (Bb * Ss) / 128, 3);
    proj_kernel<<<gp, 256>>>(q, k, v, Wq, Wk, Wv, bq, bk, bv);

    cudaFuncSetAttribute(attn_kernel, cudaFuncAttributeMaxDynamicSharedMemorySize, ATTN_SMEM);
    dim3 ga(Ss / QT, Hh, Bb);
    attn_kernel<<<ga, 512, ATTN_SMEM>>>(l1, outp, probp);
}

// round 5
// speedup vs baseline: 1.5336x; 1.5336x over previous
#include <cuda_runtime.h>

#define Bb 8
#define Ss 1024
#define Dd 768
#define Hh 12
#define HDd 64

// ---------------- device scratch (no allocations allowed) ----------------
__device__ float g_Q[(size_t)Bb * Hh * Ss * HDd];   // [B,H,S,HD]
__device__ float g_K[(size_t)Bb * Hh * Ss * HDd];
__device__ float g_V[(size_t)Bb * Hh * Ss * HDd];
__device__ float g_rel[(size_t)Bb * Ss * Ss];       // rel_attn (head-independent)
__device__ unsigned char g_mask[(size_t)Bb * Ss * Ss];
__device__ int g_mmode;

// ---------------- mask dtype detection (bool/u8 vs int32 vs float32) -----
__global__ void mask_detect_kernel(const void* mp) {
    __shared__ int allf, alli;
    if (threadIdx.x == 0) { allf = 1; alli = 1; }
    __syncthreads();
    const float* f = (const float*)mp;
    const int* w = (const int*)mp;
    float v = f[threadIdx.x];
    int iv = w[threadIdx.x];
    if (!(v == 0.0f || v == 1.0f)) allf = 0;
    if (!(iv == 0 || iv == 1)) alli = 0;
    __syncthreads();
    if (threadIdx.x == 0) g_mmode = allf ? 0 : (alli ? 1 : 2);
}

__global__ void mask_convert_kernel(const void* mp) {
    size_t i = (size_t)blockIdx.x * blockDim.x + threadIdx.x;
    int mode = g_mmode;
    unsigned char m;
    if (mode == 0)      m = (((const float*)mp)[i] != 0.0f);
    else if (mode == 1) m = (((const int*)mp)[i] != 0);
    else                m = (((const unsigned char*)mp)[i] != 0);
    g_mask[i] = m;
}

// ---------------- rel_attn softmax: one row (b,q) per block --------------
__global__ void rel_softmax_kernel(const float* __restrict__ rel) {
    int row = blockIdx.x;                       // b*S + q
    const float* r = rel + (size_t)row * Ss;
    const unsigned char* m = g_mask + (size_t)row * Ss;
    int tid = threadIdx.x;
    int w = tid >> 5, l = tid & 31;

    float v[4];
    float mx = -1e30f;
#pragma unroll
    for (int j = 0; j < 4; j++) {
        int i = tid + j * 256;
        float relm = m[i] ? r[i] : 0.0f;        // == rel * mask_float exactly
        v[j] = (relm == 0.0f) ? -10000.0f : relm;
        mx = fmaxf(mx, v[j]);
    }
    __shared__ float red[8];
#pragma unroll
    for (int o = 16; o; o >>= 1) mx = fmaxf(mx, __shfl_xor_sync(0xffffffffu, mx, o));
    if (l == 0) red[w] = mx;
    __syncthreads();
    if (w == 0) {
        float t = (l < 8) ? red[l] : -1e30f;
#pragma unroll
        for (int o = 4; o; o >>= 1) t = fmaxf(t, __shfl_xor_sync(0xffffffffu, t, o));
        if (l == 0) red[0] = t;
    }
    __syncthreads();
    mx = red[0];
    __syncthreads();

    float e[4], sum = 0.0f;
#pragma unroll
    for (int j = 0; j < 4; j++) { e[j] = expf(v[j] - mx); sum += e[j]; }
#pragma unroll
    for (int o = 16; o; o >>= 1) sum += __shfl_xor_sync(0xffffffffu, sum, o);
    if (l == 0) red[w] = sum;
    __syncthreads();
    if (w == 0) {
        float t = (l < 8) ? red[l] : 0.0f;
#pragma unroll
        for (int o = 4; o; o >>= 1) t += __shfl_xor_sync(0xffffffffu, t, o);
        if (l == 0) red[0] = t;
    }
    __syncthreads();
    float inv = 1.0f / red[0];
#pragma unroll
    for (int j = 0; j < 4; j++)
        g_rel[(size_t)row * Ss + tid + j * 256] = e[j] * inv;
}

// ---------------- fused 3-way projection GEMM ----------------------------
// C[i,j] = sum_k X[i,k] * W[j,k] + bias[j], written into [B,H,S,HD] scratch.
__global__ void proj_kernel(const float* __restrict__ Xq, const float* __restrict__ Xk, const float* __restrict__ Xv,
                            const float* __restrict__ Wq, const float* __restrict__ Wk, const float* __restrict__ Wv,
                            const float* __restrict__ bqp, const float* __restrict__ bkp, const float* __restrict__ bvp) {
    int z = blockIdx.z;
    const float* X = (z == 0) ? Xq : (z == 1) ? Xk : Xv;
    const float* W = (z == 0) ? Wq : (z == 1) ? Wk : Wv;
    const float* bias = (z == 0) ? bqp : (z == 1) ? bkp : bvp;
    float* Out = (z == 0) ? g_Q : (z == 1) ? g_K : g_V;

    __shared__ float As[16][128];
    __shared__ float Bs[16][128];
    int i0 = blockIdx.y * 128, j0 = blockIdx.x * 128;
    int tid = threadIdx.x, tx = tid & 15, ty = tid >> 4;
    float acc[8][8];
#pragma unroll
    for (int a = 0; a < 8; a++)
#pragma unroll
        for (int c = 0; c < 8; c++) acc[a][c] = 0.0f;

    int lr = tid >> 2;          // 0..63
    int lc = (tid & 3) * 4;     // 0,4,8,12

    for (int k0 = 0; k0 < Dd; k0 += 16) {
#pragma unroll
        for (int p = 0; p < 2; p++) {
            int row = lr + p * 64;
            float4 a = *(const float4*)(X + (size_t)(i0 + row) * Dd + k0 + lc);
            As[lc + 0][row] = a.x; As[lc + 1][row] = a.y; As[lc + 2][row] = a.z; As[lc + 3][row] = a.w;
            float4 w4 = *(const float4*)(W + (size_t)(j0 + row) * Dd + k0 + lc);
            Bs[lc + 0][row] = w4.x; Bs[lc + 1][row] = w4.y; Bs[lc + 2][row] = w4.z; Bs[lc + 3][row] = w4.w;
        }
        __syncthreads();
#pragma unroll
        for (int kk = 0; kk < 16; kk++) {
            float a[8], bb[8];
#pragma unroll
            for (int u = 0; u < 8; u++) a[u] = As[kk][ty * 8 + u];
#pragma unroll
            for (int u = 0; u < 8; u++) bb[u] = Bs[kk][tx * 8 + u];
#pragma unroll
            for (int ii = 0; ii < 8; ii++)
#pragma unroll
                for (int jj = 0; jj < 8; jj++) acc[ii][jj] += a[ii] * bb[jj];
        }
        __syncthreads();
    }
#pragma unroll
    for (int ii = 0; ii < 8; ii++) {
        int i = i0 + ty * 8 + ii;
        int bI = i >> 10, s = i & 1023;
#pragma unroll
        for (int jj = 0; jj < 8; jj++) {
            int j = j0 + tx * 8 + jj;
            int hI = j >> 6, hd = j & 63;
            Out[(((size_t)bI * Hh + hI) * Ss + s) * HDd + hd] = acc[ii][jj] + bias[j];
        }
    }
}

// ---------------- fused attention ---------------------------------------
// One block per (b, h, 32 q-rows). 512 threads.
// Phase1: S_tile = Q @ K^T /8, mask -> SMEM (32x1024 fp32)
// Phase2: row softmax + mix with rel_attn, write prob_attn
// Phase3: out = P @ V
#define QT 32
#define KT 128
#define SS_FLOATS (QT * Ss)        // 32768
#define SQ_FLOATS (QT * HDd)       // 2048
#define KV_FLOATS 8704             // max(64*132, 128*68)
#define ATTN_SMEM ((SS_FLOATS + SQ_FLOATS + KV_FLOATS) * 4)

__global__ void __launch_bounds__(512, 1)
attn_kernel(const float* __restrict__ l1p, float* __restrict__ outp, float* __restrict__ probp) {
    extern __shared__ float sm[];
    float* sS = sm;                  // [QT][1024] scores/probs
    float* sQ = sS + SS_FLOATS;      // [QT][64]
    float* sT = sQ + SQ_FLOATS;      // K tile: [64 dims][132] transposed ; V tile: [128 rows][68]

    int qt = blockIdx.x * QT;
    int h = blockIdx.y, b = blockIdx.z;
    int tid = threadIdx.x;
    int tx = tid & 15;               // k-group / hd-group
    int ty = tid >> 4;               // q row (0..31)
    const size_t bh = (size_t)b * Hh + h;
    const float* Qg = g_Q + (bh * Ss + qt) * HDd;
    const float* Kg = g_K + bh * Ss * HDd;
    const float* Vg = g_V + bh * Ss * HDd;

    for (int t = tid; t < QT * HDd; t += 512) sQ[t] = Qg[t];
    float l1 = *l1p, l0 = 1.0f - l1;

    // ---------------- phase 1: scores ----------------
    int kb = tx * 8;
    int q = ty;
    for (int kt = 0; kt < Ss; kt += KT) {
        __syncthreads();   // protect sT reuse + first-iter sQ visibility
        for (int t = tid; t < KT * HDd; t += 512) {
            int r = t >> 6, c = t & 63;
            sT[c * 132 + r] = Kg[(size_t)(kt + r) * HDd + c];   // [dim][krow]
        }
        __syncthreads();
        float r0[8];
#pragma unroll
        for (int u = 0; u < 8; u++) r0[u] = 0.0f;
        for (int kk = 0; kk < HDd; kk++) {
            float a0 = sQ[q * HDd + kk];
            float bv[8];
            *(float4*)(bv)     = *(const float4*)(sT + kk * 132 + kb);
            *(float4*)(bv + 4) = *(const float4*)(sT + kk * 132 + kb + 4);
#pragma unroll
            for (int u = 0; u < 8; u++) r0[u] += a0 * bv[u];
        }
        const unsigned char* m0 = g_mask + ((size_t)b * Ss + qt + q) * Ss + kt + kb;
#pragma unroll
        for (int u = 0; u < 8; u++) {
            float v0 = r0[u] * 0.125f;              // 1/sqrt(64)
            if (m0[u]) v0 = -1000000000.0f;
            sS[q * Ss + kt + kb + u] = v0;
        }
    }
    __syncthreads();

    // ---------------- phase 2: softmax + mix + prob write ----------------
    int wid = tid >> 5, lane = tid & 31;
    for (int rq = wid * 2; rq < wid * 2 + 2; rq++) {
        float* row = sS + rq * Ss;
        float mx = -1e30f;
        for (int i = lane; i < Ss; i += 32) mx = fmaxf(mx, row[i]);
#pragma unroll
        for (int o = 16; o; o >>= 1) mx = fmaxf(mx, __shfl_xor_sync(0xffffffffu, mx, o));
        float sum = 0.0f;
        for (int i = lane; i < Ss; i += 32) { float e = expf(row[i] - mx); row[i] = e; sum += e; }
#pragma unroll
        for (int o = 16; o; o >>= 1) sum += __shfl_xor_sync(0xffffffffu, sum, o);
        float inv = 1.0f / sum;
        const float* ra = g_rel + ((size_t)b * Ss + qt + rq) * Ss;
        float* pg = probp + (bh * Ss + qt + rq) * Ss;
        for (int i = lane; i < Ss; i += 32) {
            float p = l0 * row[i] * inv + l1 * ra[i];
            row[i] = p;
            pg[i] = p;
        }
    }
    __syncthreads();

    // ---------------- phase 3: out = P @ V ----------------
    int hd0 = tx * 4;
    float o0[4] = {0.0f, 0.0f, 0.0f, 0.0f};
    for (int kt = 0; kt < Ss; kt += KT) {
        for (int t = tid; t < KT * HDd; t += 512) {
            int r = t >> 6, c = t & 63;
            sT[r * 68 + c] = Vg[(size_t)(kt + r) * HDd + c];    // [krow][dim]
        }
        __syncthreads();
        for (int kk = 0; kk < KT; kk++) {
            float p0 = sS[q * Ss + kt + kk];
            float vv[4];
            *(float4*)vv = *(const float4*)(sT + kk * 68 + hd0);
#pragma unroll
            for (int u = 0; u < 4; u++) o0[u] += p0 * vv[u];
        }
        __syncthreads();
    }
    float* og = outp + ((size_t)b * Ss + qt + q) * Dd + h * HDd + hd0;
#pragma unroll
    for (int u = 0; u < 4; u++) og[u] = o0[u];
}

// ---------------- launcher ----------------------------------------------
extern "C" void kernel_launch(void* const* d_in, const int* in_sizes, int n_in,
                              void* d_out, int out_size) {
    const float* q   = (const float*)d_in[0];
    const float* k   = (const float*)d_in[1];
    const float* v   = (const float*)d_in[2];
    const float* rel = (const float*)d_in[3];
    const void*  msk = d_in[4];
    const float* l1  = (const float*)d_in[5];
    const float* Wq  = (const float*)d_in[6];
    const float* bq  = (const float*)d_in[7];
    const float* Wk  = (const float*)d_in[8];
    const float* bk  = (const float*)d_in[9];
    const float* Wv  = (const float*)d_in[10];
    const float* bv  = (const float*)d_in[11];

    float* outp = (float*)d_out;
    float* probp = outp + (size_t)Bb * Ss * Dd;   // [out | prob_attn]

    mask_detect_kernel<<<1, 256>>>(msk);
    mask_convert_kernel<<<(Bb * Ss * Ss) / 256, 256>>>(msk);
    rel_softmax_kernel<<<Bb * Ss, 256>>>(rel);

    dim3 gp(Dd / 128, (Bb * Ss) / 128, 3);
    proj_kernel<<<gp, 256>>>(q, k, v, Wq, Wk, Wv, bq, bk, bv);

    cudaFuncSetAttribute(attn_kernel, cudaFuncAttributeMaxDynamicSharedMemorySize, ATTN_SMEM);
    dim3 ga(Ss / QT, Hh, Bb);
    attn_kernel<<<ga, 512, ATTN_SMEM>>>(l1, outp, probp);
}

// round 7
// speedup vs baseline: 4.7470x; 3.0953x over previous
#include <cuda_runtime.h>
#include <cuda_bf16.h>
#include <cstdint>

#define Bb 8
#define Ss 1024
#define Dd 768
#define Hh 12
#define HDd 64
#define BH (Bb*Hh)
#define LDA 80   // padded row stride in bytes (32 bf16 + 8 pad) — conflict-free ldmatrix

// ---------------- device scratch (statics; no runtime allocs) ------------
__device__ float g_Q[(size_t)BH * Ss * HDd];      // [B,H,S,HD]
__device__ float g_K[(size_t)BH * Ss * HDd];      // [B,H,S,HD]
__device__ float g_Vt[(size_t)BH * HDd * Ss];     // [B,H,HD,S] (V transposed)
__device__ float g_scores[(size_t)BH * Ss * Ss];  // masked scaled scores
__device__ unsigned char g_mask[(size_t)Bb * Ss * Ss];
__device__ int g_mmode;

// ======================= MMA primitives (plain sm_80+ PTX) ===============
__device__ __forceinline__ unsigned smem_u32(const void* p) {
    unsigned a;
    asm("{ .reg .u64 t; cvta.to.shared.u64 t, %1; cvt.u32.u64 %0, t; }" : "=r"(a) : "l"(p));
    return a;
}
__device__ __forceinline__ void ldmA(unsigned* a, unsigned addr) {
    asm volatile("ldmatrix.sync.aligned.m8n8.x4.shared.b16 {%0,%1,%2,%3}, [%4];"
        : "=r"(a[0]), "=r"(a[1]), "=r"(a[2]), "=r"(a[3]) : "r"(addr));
}
__device__ __forceinline__ void ldmB(unsigned* b, unsigned addr) {
    asm volatile("ldmatrix.sync.aligned.m8n8.x2.shared.b16 {%0,%1}, [%2];"
        : "=r"(b[0]), "=r"(b[1]) : "r"(addr));
}
__device__ __forceinline__ void mma16816(float* d, const unsigned* a, const unsigned* b) {
    asm volatile("mma.sync.aligned.m16n8k16.row.col.f32.bf16.bf16.f32 "
        "{%0,%1,%2,%3}, {%4,%5,%6,%7}, {%8,%9}, {%0,%1,%2,%3};"
        : "+f"(d[0]), "+f"(d[1]), "+f"(d[2]), "+f"(d[3])
        : "r"(a[0]), "r"(a[1]), "r"(a[2]), "r"(a[3]), "r"(b[0]), "r"(b[1]));
}

// fp32 -> bf16 hi/lo split; store 4 elems (8B) per side at byte offset 'off'
__device__ __forceinline__ void cvt8(char* hi, char* lo, unsigned off, float4 f) {
    __nv_bfloat162 h0 = __float22bfloat162_rn(make_float2(f.x, f.y));
    __nv_bfloat162 h1 = __float22bfloat162_rn(make_float2(f.z, f.w));
    float2 g0 = __bfloat1622float2(h0);
    float2 g1 = __bfloat1622float2(h1);
    __nv_bfloat162 m0 = __float22bfloat162_rn(make_float2(f.x - g0.x, f.y - g0.y));
    __nv_bfloat162 m1 = __float22bfloat162_rn(make_float2(f.z - g1.x, f.w - g1.y));
    uint2 uh; uh.x = *(unsigned*)&h0; uh.y = *(unsigned*)&h1;
    uint2 ul; ul.x = *(unsigned*)&m0; ul.y = *(unsigned*)&m1;
    *(uint2*)(hi + off) = uh;
    *(uint2*)(lo + off) = ul;
}

template<int NF4> struct R4 { float4 v[NF4]; };
// load (NF4*256/8) rows x 32 fp32 from src into regs
template<int NF4>
__device__ __forceinline__ void gload(const float* __restrict__ src, int stride, R4<NF4>& rg, int tid) {
#pragma unroll
    for (int t = 0; t < NF4; t++) {
        int i = tid + t * 256;
        rg.v[t] = *(const float4*)(src + (long)(i >> 3) * stride + (i & 7) * 4);
    }
}
template<int NF4>
__device__ __forceinline__ void cstore(char* hi, char* lo, const R4<NF4>& rg, int tid) {
#pragma unroll
    for (int t = 0; t < NF4; t++) {
        int i = tid + t * 256;
        cvt8(hi, lo, (unsigned)((i >> 3) * LDA + (i & 7) * 8), rg.v[t]);
    }
}

// one K=32 chunk of 3-pass split MMA.
// Buffer layout: [Ahi 128*80][Alo 128*80][Bhi NB*80][Blo NB*80]
template<int NAT, int NBROWS>
__device__ __forceinline__ void mma_chunk(float (&c)[4][NAT][4], unsigned sb,
                                          int lane, int warp_m, int warp_n) {
    unsigned aOff = sb + (unsigned)(warp_m * 64 + (lane & 15)) * LDA + ((lane >> 4) & 1) * 16;
    unsigned bOff = sb + 20480u + (unsigned)(warp_n * (NAT * 8) + (lane & 7)) * LDA + ((lane >> 3) & 1) * 16;
#pragma unroll
    for (int ks = 0; ks < 2; ks++) {
        unsigned ah[4][4], al[4][4];
#pragma unroll
        for (int ma = 0; ma < 4; ma++) {
            ldmA(ah[ma], aOff + ma * 16 * LDA + ks * 32);
            ldmA(al[ma], aOff + 10240u + ma * 16 * LDA + ks * 32);
        }
#pragma unroll
        for (int na = 0; na < NAT; na++) {
            unsigned bh[2], bl[2];
            ldmB(bh, bOff + na * 8 * LDA + ks * 32);
            ldmB(bl, bOff + (unsigned)NBROWS * LDA + na * 8 * LDA + ks * 32);
#pragma unroll
            for (int ma = 0; ma < 4; ma++) {
                mma16816(c[ma][na], ah[ma], bh);
                mma16816(c[ma][na], ah[ma], bl);
                mma16816(c[ma][na], al[ma], bh);
            }
        }
    }
}

// fast exp on the FFMA pipe (~1.3e-5 rel err); avoids MUFU throughput wall
__device__ __forceinline__ float fexp(float x) {
    float t = fmaxf(x * 1.4426950408889634f, -126.0f);
    float fi = floorf(t);
    float f = t - fi;
    float p = 1.5403530394e-4f;
    p = fmaf(p, f, 1.3333558146e-3f);
    p = fmaf(p, f, 9.6181291076e-3f);
    p = fmaf(p, f, 5.5504108664e-2f);
    p = fmaf(p, f, 2.4022650696e-1f);
    p = fmaf(p, f, 6.9314718056e-1f);
    p = fmaf(p, f, 1.0f);
    return p * __int_as_float(((int)fi + 127) << 23);
}

// ---------------- mask detect + convert ----------------------------------
__global__ void mask_detect_kernel(const void* mp) {
    __shared__ int allf, alli;
    if (threadIdx.x == 0) { allf = 1; alli = 1; }
    __syncthreads();
    float v = ((const float*)mp)[threadIdx.x];
    int iv = ((const int*)mp)[threadIdx.x];
    if (!(v == 0.0f || v == 1.0f)) allf = 0;
    if (!(iv == 0 || iv == 1)) alli = 0;
    __syncthreads();
    if (threadIdx.x == 0) g_mmode = allf ? 0 : (alli ? 1 : 2);
}
__global__ void mask_convert_kernel(const void* mp) {
    size_t i = (size_t)blockIdx.x * blockDim.x + threadIdx.x;
    int mode = g_mmode;
    unsigned char m;
    if (mode == 0)      m = (((const float*)mp)[i] != 0.0f);
    else if (mode == 1) m = (((const int*)mp)[i] != 0);
    else                m = (((const unsigned char*)mp)[i] != 0);
    g_mask[i] = m;
}

// ================= projection GEMM (bf16x3 mma.sync) =====================
// C[i,j] = sum_k X[i,k]*W[j,k] + bias[j]. z: 0=Q,1=K -> [B,H,S,HD]; 2=V -> [B,H,HD,S]
#define PROJ_SMEM (2 * 40960)
__global__ void __launch_bounds__(256, 1)
proj_mma(const float* __restrict__ Xq, const float* __restrict__ Xk, const float* __restrict__ Xv,
         const float* __restrict__ Wq, const float* __restrict__ Wk, const float* __restrict__ Wv,
         const float* __restrict__ bqp, const float* __restrict__ bkp, const float* __restrict__ bvp) {
    extern __shared__ char sm[];
    unsigned smb = smem_u32(sm);
    int tid = threadIdx.x, lane = tid & 31, wid = tid >> 5;
    int warp_m = wid >> 2, warp_n = wid & 3;
    int z = blockIdx.z;
    const float* X = (z == 0) ? Xq : (z == 1) ? Xk : Xv;
    const float* W = (z == 0) ? Wq : (z == 1) ? Wk : Wv;
    const float* bias = (z == 0) ? bqp : (z == 1) ? bkp : bvp;
    int j0 = blockIdx.x * 128, i0 = blockIdx.y * 128;

    float acc[4][4][4];
#pragma unroll
    for (int a = 0; a < 4; a++)
#pragma unroll
        for (int b = 0; b < 4; b++)
#pragma unroll
            for (int r = 0; r < 4; r++) acc[a][b][r] = 0.0f;

    const float* A0 = X + (size_t)i0 * Dd;
    const float* B0 = W + (size_t)j0 * Dd;
    R4<4> ra, rb;
    gload<4>(A0, Dd, ra, tid);
    gload<4>(B0, Dd, rb, tid);
    cstore<4>(sm, sm + 10240, ra, tid);
    cstore<4>(sm + 20480, sm + 30720, rb, tid);
    __syncthreads();

    const int NC = Dd / 32;   // 24
    for (int cc = 0; cc < NC; cc++) {
        if (cc + 1 < NC) {
            gload<4>(A0 + (cc + 1) * 32, Dd, ra, tid);
            gload<4>(B0 + (cc + 1) * 32, Dd, rb, tid);
        }
        mma_chunk<4, 128>(acc, smb + (unsigned)(cc & 1) * 40960u, lane, warp_m, warp_n);
        if (cc + 1 < NC) {
            char* bn = sm + ((cc + 1) & 1) * 40960;
            cstore<4>(bn, bn + 10240, ra, tid);
            cstore<4>(bn + 20480, bn + 30720, rb, tid);
        }
        __syncthreads();
    }

    int bI = i0 >> 10, sbase = i0 & 1023;
    float bias2[4][2];
#pragma unroll
    for (int na = 0; na < 4; na++) {
        int n0 = warp_n * 32 + na * 8 + (lane & 3) * 2;
        bias2[na][0] = bias[j0 + n0];
        bias2[na][1] = bias[j0 + n0 + 1];
    }
    if (z == 2) {
#pragma unroll
        for (int ma = 0; ma < 4; ma++)
#pragma unroll
            for (int na = 0; na < 4; na++)
#pragma unroll
                for (int rp = 0; rp < 2; rp++) {
                    int m = warp_m * 64 + ma * 16 + (lane >> 2) + rp * 8;
                    int n0 = warp_n * 32 + na * 8 + (lane & 3) * 2;
                    int j = j0 + n0, h = j >> 6, hd = j & 63;
                    int s = sbase + m;
                    size_t base = ((size_t)bI * Hh + h) * HDd;
                    g_Vt[(base + hd)     * Ss + s] = acc[ma][na][rp * 2]     + bias2[na][0];
                    g_Vt[(base + hd + 1) * Ss + s] = acc[ma][na][rp * 2 + 1] + bias2[na][1];
                }
    } else {
        float* Out = (z == 0) ? g_Q : g_K;
#pragma unroll
        for (int ma = 0; ma < 4; ma++)
#pragma unroll
            for (int na = 0; na < 4; na++)
#pragma unroll
                for (int rp = 0; rp < 2; rp++) {
                    int m = warp_m * 64 + ma * 16 + (lane >> 2) + rp * 8;
                    int n0 = warp_n * 32 + na * 8 + (lane & 3) * 2;
                    int j = j0 + n0, h = j >> 6, hd = j & 63;
                    float2 v;
                    v.x = acc[ma][na][rp * 2]     + bias2[na][0];
                    v.y = acc[ma][na][rp * 2 + 1] + bias2[na][1];
                    *(float2*)(Out + (((size_t)bI * Hh + h) * Ss + sbase + m) * HDd + hd) = v;
                }
    }
}

// ================= scores GEMM: S = QK^T/8 + mask ========================
#define SCORES_SMEM (2 * 40960)
__global__ void __launch_bounds__(256, 1)
scores_mma() {
    extern __shared__ char sm[];
    unsigned smb = smem_u32(sm);
    int tid = threadIdx.x, lane = tid & 31, wid = tid >> 5;
    int warp_m = wid >> 2, warp_n = wid & 3;
    int k0 = blockIdx.x * 128, q0 = blockIdx.y * 128, bh = blockIdx.z;
    int b_ = bh / Hh;

    float acc[4][4][4];
#pragma unroll
    for (int a = 0; a < 4; a++)
#pragma unroll
        for (int b = 0; b < 4; b++)
#pragma unroll
            for (int r = 0; r < 4; r++) acc[a][b][r] = 0.0f;

    const float* A0 = g_Q + ((size_t)bh * Ss + q0) * HDd;
    const float* B0 = g_K + ((size_t)bh * Ss + k0) * HDd;
    R4<4> ra, rb;
    gload<4>(A0, HDd, ra, tid);
    gload<4>(B0, HDd, rb, tid);
    cstore<4>(sm, sm + 10240, ra, tid);
    cstore<4>(sm + 20480, sm + 30720, rb, tid);
    __syncthreads();

    const int NC = HDd / 32;   // 2
    for (int cc = 0; cc < NC; cc++) {
        if (cc + 1 < NC) {
            gload<4>(A0 + (cc + 1) * 32, HDd, ra, tid);
            gload<4>(B0 + (cc + 1) * 32, HDd, rb, tid);
        }
        mma_chunk<4, 128>(acc, smb + (unsigned)(cc & 1) * 40960u, lane, warp_m, warp_n);
        if (cc + 1 < NC) {
            char* bn = sm + ((cc + 1) & 1) * 40960;
            cstore<4>(bn, bn + 10240, ra, tid);
            cstore<4>(bn + 20480, bn + 30720, rb, tid);
        }
        __syncthreads();
    }

#pragma unroll
    for (int ma = 0; ma < 4; ma++)
#pragma unroll
        for (int na = 0; na < 4; na++)
#pragma unroll
            for (int rp = 0; rp < 2; rp++) {
                int m = warp_m * 64 + ma * 16 + (lane >> 2) + rp * 8;
                int n0 = warp_n * 32 + na * 8 + (lane & 3) * 2;
                int q = q0 + m, k = k0 + n0;
                uchar2 mk = *(const uchar2*)(g_mask + ((size_t)b_ * Ss + q) * Ss + k);
                float2 v;
                v.x = mk.x ? -1000000000.0f : acc[ma][na][rp * 2]     * 0.125f;
                v.y = mk.y ? -1000000000.0f : acc[ma][na][rp * 2 + 1] * 0.125f;
                *(float2*)(g_scores + ((size_t)bh * Ss + q) * Ss + k) = v;
            }
}

// ======= fused rel-softmax (once per (b,q)) + score-softmax + mix ========
__device__ __forceinline__ float blk_red(float v, float* red, int wid, int lane, bool ismax) {
#pragma unroll
    for (int o = 16; o; o >>= 1) {
        float t = __shfl_xor_sync(0xffffffffu, v, o);
        v = ismax ? fmaxf(v, t) : v + t;
    }
    if (lane == 0) red[wid] = v;
    __syncthreads();
    if (wid == 0) {
        float t = (lane < 8) ? red[lane] : (ismax ? -3e38f : 0.0f);
#pragma unroll
        for (int o = 4; o; o >>= 1) {
            float u = __shfl_xor_sync(0xffffffffu, t, o);
            t = ismax ? fmaxf(t, u) : t + u;
        }
        if (lane == 0) red[0] = t;
    }
    __syncthreads();
    float r = red[0];
    __syncthreads();
    return r;
}

__global__ void __launch_bounds__(256)
softmax_mix_kernel(const float* __restrict__ rel, const float* __restrict__ l1p,
                   float* __restrict__ probp) {
    __shared__ float red[8];
    int bq = blockIdx.x;
    int b = bq >> 10, q = bq & 1023;
    int tid = threadIdx.x, wid = tid >> 5, lane = tid & 31;
    size_t rowoff = (size_t)bq * Ss + tid * 4;

    // ---- rel_attn row (head-independent, kept in registers) ----
    float4 rf = *(const float4*)(rel + rowoff);
    uchar4 mk = *(const uchar4*)(g_mask + rowoff);
    float vv[4];
    vv[0] = mk.x ? rf.x : 0.0f; vv[1] = mk.y ? rf.y : 0.0f;
    vv[2] = mk.z ? rf.z : 0.0f; vv[3] = mk.w ? rf.w : 0.0f;
    float mx = -3e38f;
#pragma unroll
    for (int u = 0; u < 4; u++) {
        vv[u] = (vv[u] == 0.0f) ? -10000.0f : vv[u];
        mx = fmaxf(mx, vv[u]);
    }
    mx = blk_red(mx, red, wid, lane, true);
    float ra[4], s = 0.0f;
#pragma unroll
    for (int u = 0; u < 4; u++) { ra[u] = fexp(vv[u] - mx); s += ra[u]; }
    s = blk_red(s, red, wid, lane, false);
    float l1 = *l1p, l0 = 1.0f - l1;
    float sc1 = l1 / s;
#pragma unroll
    for (int u = 0; u < 4; u++) ra[u] *= sc1;

    // ---- per-head score softmax + mix ----
    for (int h = 0; h < Hh; h++) {
        size_t off = ((size_t)(b * Hh + h) * Ss + q) * Ss + tid * 4;
        float4 sv = *(const float4*)(g_scores + off);
        float m2 = fmaxf(fmaxf(sv.x, sv.y), fmaxf(sv.z, sv.w));
        m2 = blk_red(m2, red, wid, lane, true);
        float e0 = fexp(sv.x - m2), e1 = fexp(sv.y - m2);
        float e2 = fexp(sv.z - m2), e3 = fexp(sv.w - m2);
        float su = blk_red(e0 + e1 + e2 + e3, red, wid, lane, false);
        float iv = l0 / su;
        float4 o;
        o.x = fmaf(e0, iv, ra[0]); o.y = fmaf(e1, iv, ra[1]);
        o.z = fmaf(e2, iv, ra[2]); o.w = fmaf(e3, iv, ra[3]);
        *(float4*)(probp + off) = o;
    }
}

// ================= PV GEMM: out = P @ V ==================================
// tile 128(q) x 64(hd); B = g_Vt (n-major rows, 64)
#define PV_SMEM (2 * 30720)
__global__ void __launch_bounds__(256, 1)
pv_mma(const float* __restrict__ probp, float* __restrict__ outp) {
    extern __shared__ char sm[];
    unsigned smb = smem_u32(sm);
    int tid = threadIdx.x, lane = tid & 31, wid = tid >> 5;
    int warp_m = wid >> 2, warp_n = wid & 3;
    int q0 = blockIdx.x * 128, bh = blockIdx.y;
    int b_ = bh / Hh, h_ = bh % Hh;

    float acc[4][2][4];
#pragma unroll
    for (int a = 0; a < 4; a++)
#pragma unroll
        for (int b = 0; b < 2; b++)
#pragma unroll
            for (int r = 0; r < 4; r++) acc[a][b][r] = 0.0f;

    const float* A0 = probp + ((size_t)bh * Ss + q0) * Ss;
    const float* B0 = g_Vt + (size_t)bh * HDd * Ss;
    R4<4> ra; R4<2> rb;
    gload<4>(A0, Ss, ra, tid);
    gload<2>(B0, Ss, rb, tid);
    cstore<4>(sm, sm + 10240, ra, tid);
    cstore<2>(sm + 20480, sm + 25600, rb, tid);
    __syncthreads();

    const int NC = Ss / 32;   // 32
    for (int cc = 0; cc < NC; cc++) {
        if (cc + 1 < NC) {
            gload<4>(A0 + (cc + 1) * 32, Ss, ra, tid);
            gload<2>(B0 + (cc + 1) * 32, Ss, rb, tid);
        }
        mma_chunk<2, 64>(acc, smb + (unsigned)(cc & 1) * 30720u, lane, warp_m, warp_n);
        if (cc + 1 < NC) {
            char* bn = sm + ((cc + 1) & 1) * 30720;
            cstore<4>(bn, bn + 10240, ra, tid);
            cstore<2>(bn + 20480, bn + 25600, rb, tid);
        }
        __syncthreads();
    }

#pragma unroll
    for (int ma = 0; ma < 4; ma++)
#pragma unroll
        for (int na = 0; na < 2; na++)
#pragma unroll
            for (int rp = 0; rp < 2; rp++) {
                int m = warp_m * 64 + ma * 16 + (lane >> 2) + rp * 8;
                int n0 = warp_n * 16 + na * 8 + (lane & 3) * 2;
                float2 v;
                v.x = acc[ma][na][rp * 2];
                v.y = acc[ma][na][rp * 2 + 1];
                *(float2*)(outp + ((size_t)b_ * Ss + q0 + m) * Dd + h_ * HDd + n0) = v;
            }
}

// ---------------- launcher ----------------------------------------------
extern "C" void kernel_launch(void* const* d_in, const int* in_sizes, int n_in,
                              void* d_out, int out_size) {
    const float* q   = (const float*)d_in[0];
    const float* k   = (const float*)d_in[1];
    const float* v   = (const float*)d_in[2];
    const float* rel = (const float*)d_in[3];
    const void*  msk = d_in[4];
    const float* l1  = (const float*)d_in[5];
    const float* Wq  = (const float*)d_in[6];
    const float* bq  = (const float*)d_in[7];
    const float* Wk  = (const float*)d_in[8];
    const float* bk  = (const float*)d_in[9];
    const float* Wv  = (const float*)d_in[10];
    const float* bv  = (const float*)d_in[11];

    float* outp = (float*)d_out;
    float* probp = outp + (size_t)Bb * Ss * Dd;

    cudaFuncSetAttribute(proj_mma,   cudaFuncAttributeMaxDynamicSharedMemorySize, PROJ_SMEM);
    cudaFuncSetAttribute(scores_mma, cudaFuncAttributeMaxDynamicSharedMemorySize, SCORES_SMEM);
    cudaFuncSetAttribute(pv_mma,     cudaFuncAttributeMaxDynamicSharedMemorySize, PV_SMEM);

    mask_detect_kernel<<<1, 256>>>(msk);
    mask_convert_kernel<<<(Bb * Ss * Ss) / 256, 256>>>(msk);

    dim3 gp(Dd / 128, (Bb * Ss) / 128, 3);
    proj_mma<<<gp, 256, PROJ_SMEM>>>(q, k, v, Wq, Wk, Wv, bq, bk, bv);

    dim3 gs(Ss / 128, Ss / 128, BH);
    scores_mma<<<gs, 256, SCORES_SMEM>>>();

    softmax_mix_kernel<<<Bb * Ss, 256>>>(rel, l1, probp);

    dim3 gv(Ss / 128, BH);
    pv_mma<<<gv, 256, PV_SMEM>>>(probp, outp);
}

// round 8
// speedup vs baseline: 6.5898x; 1.3882x over previous
#include <cuda_runtime.h>
#include <cuda_bf16.h>
#include <cstdint>

#define Bb 8
#define Ss 1024
#define Dd 768
#define Hh 12
#define HDd 64
#define BH (Bb*Hh)
#define LDA 80    // 32 bf16 + 8B pad (proj/pv tiles)
#define LDA64 144 // 64 bf16 + 16B pad (fused-attn tiles)

// ---------------- device scratch (statics; no runtime allocs) ------------
__device__ float g_Q[(size_t)BH * Ss * HDd];      // [B,H,S,HD]
__device__ float g_K[(size_t)BH * Ss * HDd];      // [B,H,S,HD]
__device__ float g_Vt[(size_t)BH * HDd * Ss];     // [B,H,HD,S] (V transposed)
__device__ float g_rel[(size_t)Bb * Ss * Ss];     // rel_attn (head-independent)
__device__ unsigned char g_mask[(size_t)Bb * Ss * Ss];
__device__ int g_mmode;

// ======================= MMA primitives (plain sm_80+ PTX) ===============
__device__ __forceinline__ unsigned smem_u32(const void* p) {
    unsigned a;
    asm("{ .reg .u64 t; cvta.to.shared.u64 t, %1; cvt.u32.u64 %0, t; }" : "=r"(a) : "l"(p));
    return a;
}
__device__ __forceinline__ void ldmA(unsigned* a, unsigned addr) {
    asm volatile("ldmatrix.sync.aligned.m8n8.x4.shared.b16 {%0,%1,%2,%3}, [%4];"
        : "=r"(a[0]), "=r"(a[1]), "=r"(a[2]), "=r"(a[3]) : "r"(addr));
}
__device__ __forceinline__ void ldmB(unsigned* b, unsigned addr) {
    asm volatile("ldmatrix.sync.aligned.m8n8.x2.shared.b16 {%0,%1}, [%2];"
        : "=r"(b[0]), "=r"(b[1]) : "r"(addr));
}
__device__ __forceinline__ void mma16816(float* d, const unsigned* a, const unsigned* b) {
    asm volatile("mma.sync.aligned.m16n8k16.row.col.f32.bf16.bf16.f32 "
        "{%0,%1,%2,%3}, {%4,%5,%6,%7}, {%8,%9}, {%0,%1,%2,%3};"
        : "+f"(d[0]), "+f"(d[1]), "+f"(d[2]), "+f"(d[3])
        : "r"(a[0]), "r"(a[1]), "r"(a[2]), "r"(a[3]), "r"(b[0]), "r"(b[1]));
}

// fp32 -> bf16 hi/lo split; store 4 elems (8B) per side at byte offset 'off'
__device__ __forceinline__ void cvt8(char* hi, char* lo, unsigned off, float4 f) {
    __nv_bfloat162 h0 = __float22bfloat162_rn(make_float2(f.x, f.y));
    __nv_bfloat162 h1 = __float22bfloat162_rn(make_float2(f.z, f.w));
    float2 g0 = __bfloat1622float2(h0);
    float2 g1 = __bfloat1622float2(h1);
    __nv_bfloat162 m0 = __float22bfloat162_rn(make_float2(f.x - g0.x, f.y - g0.y));
    __nv_bfloat162 m1 = __float22bfloat162_rn(make_float2(f.z - g1.x, f.w - g1.y));
    uint2 uh; uh.x = *(unsigned*)&h0; uh.y = *(unsigned*)&h1;
    uint2 ul; ul.x = *(unsigned*)&m0; ul.y = *(unsigned*)&m1;
    *(uint2*)(hi + off) = uh;
    *(uint2*)(lo + off) = ul;
}

template<int NF4> struct R4 { float4 v[NF4]; };
// 8 threads/row (32-col tiles)
template<int NF4>
__device__ __forceinline__ void gload(const float* __restrict__ src, int stride, R4<NF4>& rg, int tid) {
#pragma unroll
    for (int t = 0; t < NF4; t++) {
        int i = tid + t * 256;
        rg.v[t] = *(const float4*)(src + (long)(i >> 3) * stride + (i & 7) * 4);
    }
}
template<int NF4>
__device__ __forceinline__ void cstore(char* hi, char* lo, const R4<NF4>& rg, int tid) {
#pragma unroll
    for (int t = 0; t < NF4; t++) {
        int i = tid + t * 256;
        cvt8(hi, lo, (unsigned)((i >> 3) * LDA + (i & 7) * 8), rg.v[t]);
    }
}
// 16 threads/row (64-col tiles, LDA64 stride)
template<int NF4>
__device__ __forceinline__ void gload64(const float* __restrict__ src, int stride, R4<NF4>& rg, int tid) {
#pragma unroll
    for (int t = 0; t < NF4; t++) {
        int i = tid + t * 256;
        rg.v[t] = *(const float4*)(src + (long)(i >> 4) * stride + (i & 15) * 4);
    }
}
template<int NF4>
__device__ __forceinline__ void cstore64(char* hi, char* lo, const R4<NF4>& rg, int tid) {
#pragma unroll
    for (int t = 0; t < NF4; t++) {
        int i = tid + t * 256;
        cvt8(hi, lo, (unsigned)((i >> 4) * LDA64 + (i & 15) * 8), rg.v[t]);
    }
}

// one K=32 chunk of 3-pass split MMA (proj/pv: 128-row A, LDA=80)
template<int NAT, int NBROWS>
__device__ __forceinline__ void mma_chunk(float (&c)[4][NAT][4], unsigned sb,
                                          int lane, int warp_m, int warp_n) {
    unsigned aOff = sb + (unsigned)(warp_m * 64 + (lane & 15)) * LDA + ((lane >> 4) & 1) * 16;
    unsigned bOff = sb + 20480u + (unsigned)(warp_n * (NAT * 8) + (lane & 7)) * LDA + ((lane >> 3) & 1) * 16;
#pragma unroll
    for (int ks = 0; ks < 2; ks++) {
        unsigned ah[4][4], al[4][4];
#pragma unroll
        for (int ma = 0; ma < 4; ma++) {
            ldmA(ah[ma], aOff + ma * 16 * LDA + ks * 32);
            ldmA(al[ma], aOff + 10240u + ma * 16 * LDA + ks * 32);
        }
#pragma unroll
        for (int na = 0; na < NAT; na++) {
            unsigned bh[2], bl[2];
            ldmB(bh, bOff + na * 8 * LDA + ks * 32);
            ldmB(bl, bOff + (unsigned)NBROWS * LDA + na * 8 * LDA + ks * 32);
#pragma unroll
            for (int ma = 0; ma < 4; ma++) {
                mma16816(c[ma][na], ah[ma], bh);
                mma16816(c[ma][na], ah[ma], bl);
                mma16816(c[ma][na], al[ma], bh);
            }
        }
    }
}

// fast exp on the FFMA pipe (~1.3e-5 rel err)
__device__ __forceinline__ float fexp(float x) {
    float t = fmaxf(x * 1.4426950408889634f, -126.0f);
    float fi = floorf(t);
    float f = t - fi;
    float p = 1.5403530394e-4f;
    p = fmaf(p, f, 1.3333558146e-3f);
    p = fmaf(p, f, 9.6181291076e-3f);
    p = fmaf(p, f, 5.5504108664e-2f);
    p = fmaf(p, f, 2.4022650696e-1f);
    p = fmaf(p, f, 6.9314718056e-1f);
    p = fmaf(p, f, 1.0f);
    return p * __int_as_float(((int)fi + 127) << 23);
}

// ---------------- mask detect + convert ----------------------------------
__global__ void mask_detect_kernel(const void* mp) {
    __shared__ int allf, alli;
    if (threadIdx.x == 0) { allf = 1; alli = 1; }
    __syncthreads();
    float v = ((const float*)mp)[threadIdx.x];
    int iv = ((const int*)mp)[threadIdx.x];
    if (!(v == 0.0f || v == 1.0f)) allf = 0;
    if (!(iv == 0 || iv == 1)) alli = 0;
    __syncthreads();
    if (threadIdx.x == 0) g_mmode = allf ? 0 : (alli ? 1 : 2);
}
__global__ void mask_convert_kernel(const void* mp) {
    size_t i = (size_t)blockIdx.x * blockDim.x + threadIdx.x;
    int mode = g_mmode;
    unsigned char m;
    if (mode == 0)      m = (((const float*)mp)[i] != 0.0f);
    else if (mode == 1) m = (((const int*)mp)[i] != 0);
    else                m = (((const unsigned char*)mp)[i] != 0);
    g_mask[i] = m;
}

// ---------------- rel_attn softmax (head-independent, once per (b,q)) ----
__global__ void __launch_bounds__(256)
rel_softmax_kernel(const float* __restrict__ rel) {
    __shared__ float red[8];
    int row = blockIdx.x;                       // b*S + q
    const float* r = rel + (size_t)row * Ss;
    const unsigned char* m = g_mask + (size_t)row * Ss;
    int tid = threadIdx.x, w = tid >> 5, l = tid & 31;

    float4 rf = *(const float4*)(r + tid * 4);
    uchar4 mk = *(const uchar4*)(m + tid * 4);
    float v[4];
    v[0] = mk.x ? rf.x : 0.0f; v[1] = mk.y ? rf.y : 0.0f;
    v[2] = mk.z ? rf.z : 0.0f; v[3] = mk.w ? rf.w : 0.0f;
    float mx = -3e38f;
#pragma unroll
    for (int j = 0; j < 4; j++) {
        v[j] = (v[j] == 0.0f) ? -10000.0f : v[j];
        mx = fmaxf(mx, v[j]);
    }
#pragma unroll
    for (int o = 16; o; o >>= 1) mx = fmaxf(mx, __shfl_xor_sync(0xffffffffu, mx, o));
    if (l == 0) red[w] = mx;
    __syncthreads();
    if (w == 0) {
        float t = (l < 8) ? red[l] : -3e38f;
#pragma unroll
        for (int o = 4; o; o >>= 1) t = fmaxf(t, __shfl_xor_sync(0xffffffffu, t, o));
        if (l == 0) red[0] = t;
    }
    __syncthreads();
    mx = red[0];
    __syncthreads();
    float e[4], sum = 0.0f;
#pragma unroll
    for (int j = 0; j < 4; j++) { e[j] = fexp(v[j] - mx); sum += e[j]; }
#pragma unroll
    for (int o = 16; o; o >>= 1) sum += __shfl_xor_sync(0xffffffffu, sum, o);
    if (l == 0) red[w] = sum;
    __syncthreads();
    if (w == 0) {
        float t = (l < 8) ? red[l] : 0.0f;
#pragma unroll
        for (int o = 4; o; o >>= 1) t += __shfl_xor_sync(0xffffffffu, t, o);
        if (l == 0) red[0] = t;
    }
    __syncthreads();
    float inv = 1.0f / red[0];
    float4 o;
    o.x = e[0] * inv; o.y = e[1] * inv; o.z = e[2] * inv; o.w = e[3] * inv;
    *(float4*)(g_rel + (size_t)row * Ss + tid * 4) = o;
}

// ================= projection GEMM (bf16x3 mma.sync) =====================
#define PROJ_SMEM (2 * 40960)
__global__ void __launch_bounds__(256, 1)
proj_mma(const float* __restrict__ Xq, const float* __restrict__ Xk, const float* __restrict__ Xv,
         const float* __restrict__ Wq, const float* __restrict__ Wk, const float* __restrict__ Wv,
         const float* __restrict__ bqp, const float* __restrict__ bkp, const float* __restrict__ bvp) {
    extern __shared__ char sm[];
    unsigned smb = smem_u32(sm);
    int tid = threadIdx.x, lane = tid & 31, wid = tid >> 5;
    int warp_m = wid >> 2, warp_n = wid & 3;
    int z = blockIdx.z;
    const float* X = (z == 0) ? Xq : (z == 1) ? Xk : Xv;
    const float* W = (z == 0) ? Wq : (z == 1) ? Wk : Wv;
    const float* bias = (z == 0) ? bqp : (z == 1) ? bkp : bvp;
    int j0 = blockIdx.x * 128, i0 = blockIdx.y * 128;

    float acc[4][4][4];
#pragma unroll
    for (int a = 0; a < 4; a++)
#pragma unroll
        for (int b = 0; b < 4; b++)
#pragma unroll
            for (int r = 0; r < 4; r++) acc[a][b][r] = 0.0f;

    const float* A0 = X + (size_t)i0 * Dd;
    const float* B0 = W + (size_t)j0 * Dd;
    R4<4> ra, rb;
    gload<4>(A0, Dd, ra, tid);
    gload<4>(B0, Dd, rb, tid);
    cstore<4>(sm, sm + 10240, ra, tid);
    cstore<4>(sm + 20480, sm + 30720, rb, tid);
    __syncthreads();

    const int NC = Dd / 32;
    for (int cc = 0; cc < NC; cc++) {
        if (cc + 1 < NC) {
            gload<4>(A0 + (cc + 1) * 32, Dd, ra, tid);
            gload<4>(B0 + (cc + 1) * 32, Dd, rb, tid);
        }
        mma_chunk<4, 128>(acc, smb + (unsigned)(cc & 1) * 40960u, lane, warp_m, warp_n);
        if (cc + 1 < NC) {
            char* bn = sm + ((cc + 1) & 1) * 40960;
            cstore<4>(bn, bn + 10240, ra, tid);
            cstore<4>(bn + 20480, bn + 30720, rb, tid);
        }
        __syncthreads();
    }

    int bI = i0 >> 10, sbase = i0 & 1023;
    float bias2[4][2];
#pragma unroll
    for (int na = 0; na < 4; na++) {
        int n0 = warp_n * 32 + na * 8 + (lane & 3) * 2;
        bias2[na][0] = bias[j0 + n0];
        bias2[na][1] = bias[j0 + n0 + 1];
    }
    if (z == 2) {
#pragma unroll
        for (int ma = 0; ma < 4; ma++)
#pragma unroll
            for (int na = 0; na < 4; na++)
#pragma unroll
                for (int rp = 0; rp < 2; rp++) {
                    int m = warp_m * 64 + ma * 16 + (lane >> 2) + rp * 8;
                    int n0 = warp_n * 32 + na * 8 + (lane & 3) * 2;
                    int j = j0 + n0, h = j >> 6, hd = j & 63;
                    int s = sbase + m;
                    size_t base = ((size_t)bI * Hh + h) * HDd;
                    g_Vt[(base + hd)     * Ss + s] = acc[ma][na][rp * 2]     + bias2[na][0];
                    g_Vt[(base + hd + 1) * Ss + s] = acc[ma][na][rp * 2 + 1] + bias2[na][1];
                }
    } else {
        float* Out = (z == 0) ? g_Q : g_K;
#pragma unroll
        for (int ma = 0; ma < 4; ma++)
#pragma unroll
            for (int na = 0; na < 4; na++)
#pragma unroll
                for (int rp = 0; rp < 2; rp++) {
                    int m = warp_m * 64 + ma * 16 + (lane >> 2) + rp * 8;
                    int n0 = warp_n * 32 + na * 8 + (lane & 3) * 2;
                    int j = j0 + n0, h = j >> 6, hd = j & 63;
                    float2 v;
                    v.x = acc[ma][na][rp * 2]     + bias2[na][0];
                    v.y = acc[ma][na][rp * 2 + 1] + bias2[na][1];
                    *(float2*)(Out + (((size_t)bI * Hh + h) * Ss + sbase + m) * HDd + hd) = v;
                }
    }
}

// ====== fused attention: QK^T -> mask/scale -> softmax -> mix -> prob =====
// block = (qtile of 32, h, b); 256 threads; scores 32x1024 fp32 in SMEM.
// SMEM: [scores 32*1028*4 = 131584][Ahi 4608][Alo 4608][Kbuf0 hi+lo 36864][Kbuf1 36864]
#define FA_SCORES 0
#define FA_A      131584
#define FA_ALO    (FA_A + 4608)
#define FA_K      (FA_ALO + 4608)
#define FA_KBUF   36864
#define FA_KLO    18432
#define FA_SMEM   (FA_K + 2 * FA_KBUF)   // 214528
__global__ void __launch_bounds__(256, 1)
fused_attn(const float* __restrict__ l1p, float* __restrict__ probp) {
    extern __shared__ char sm[];
    unsigned smb = smem_u32(sm);
    float* sS = (float*)sm;
    int tid = threadIdx.x, lane = tid & 31, wid = tid >> 5;
    int warp_m = wid >> 2, warp_n = wid & 3;       // 2 x 4 warp grid (16q x 32k)
    int q0 = blockIdx.x * 32, h = blockIdx.y, b = blockIdx.z;
    size_t bh = (size_t)b * Hh + h;
    const float* Qg = g_Q + (bh * Ss + q0) * HDd;
    const float* Kg = g_K + bh * Ss * HDd;

    // load Q (32x64) -> bf16 hi/lo split
    {
        R4<2> rq;
        gload64<2>(Qg, HDd, rq, tid);
        cstore64<2>(sm + FA_A, sm + FA_ALO, rq, tid);
    }
    // K tile 0 (128x64)
    R4<8> rk;
    gload64<8>(Kg, HDd, rk, tid);
    cstore64<8>(sm + FA_K, sm + FA_K + FA_KLO, rk, tid);
    __syncthreads();

    unsigned aBase = smb + FA_A + (unsigned)(warp_m * 16 + (lane & 15)) * LDA64 + ((lane >> 4) & 1) * 16;
    // ---------------- phase 1: scores into SMEM ----------------
    for (int kt = 0; kt < 8; kt++) {
        if (kt < 7) gload64<8>(Kg + (kt + 1) * 128 * HDd, HDd, rk, tid);
        unsigned bBase = smb + FA_K + (unsigned)(kt & 1) * FA_KBUF
                       + (unsigned)(warp_n * 32 + (lane & 7)) * LDA64 + ((lane >> 3) & 1) * 16;
        float acc[4][4];
#pragma unroll
        for (int na = 0; na < 4; na++)
#pragma unroll
            for (int r = 0; r < 4; r++) acc[na][r] = 0.0f;
#pragma unroll
        for (int ks = 0; ks < 4; ks++) {
            unsigned ah[4], al[4];
            ldmA(ah, aBase + ks * 32);
            ldmA(al, aBase + 4608 + ks * 32);
#pragma unroll
            for (int na = 0; na < 4; na++) {
                unsigned bhF[2], blF[2];
                ldmB(bhF, bBase + na * 8 * LDA64 + ks * 32);
                ldmB(blF, bBase + FA_KLO + na * 8 * LDA64 + ks * 32);
                mma16816(acc[na], ah, bhF);
                mma16816(acc[na], ah, blF);
                mma16816(acc[na], al, bhF);
            }
        }
        // write raw scores to smem (stride 1028 -> conflict-free across rows)
#pragma unroll
        for (int na = 0; na < 4; na++)
#pragma unroll
            for (int rp = 0; rp < 2; rp++) {
                int m = warp_m * 16 + (lane >> 2) + rp * 8;
                int n = kt * 128 + warp_n * 32 + na * 8 + (lane & 3) * 2;
                float2 v; v.x = acc[na][rp * 2]; v.y = acc[na][rp * 2 + 1];
                *(float2*)(sS + m * 1028 + n) = v;
            }
        if (kt < 7) {
            char* bn = sm + FA_K + ((kt + 1) & 1) * FA_KBUF;
            cstore64<8>(bn, bn + FA_KLO, rk, tid);
        }
        __syncthreads();
    }

    // ---------------- phase 2: per-row softmax + mix + prob write ---------
    float l1 = *l1p, l0 = 1.0f - l1;
#pragma unroll
    for (int rr = 0; rr < 4; rr++) {
        int row = wid * 4 + rr;
        const unsigned char* mrow = g_mask + ((size_t)b * Ss + q0 + row) * Ss;
        float v[32];
        float mx = -3e38f;
#pragma unroll
        for (int j = 0; j < 8; j++) {
            int col = lane * 4 + j * 128;
            float4 s4 = *(const float4*)(sS + row * 1028 + col);
            uchar4 mk = *(const uchar4*)(mrow + col);
            v[j * 4 + 0] = mk.x ? -1000000000.0f : s4.x * 0.125f;
            v[j * 4 + 1] = mk.y ? -1000000000.0f : s4.y * 0.125f;
            v[j * 4 + 2] = mk.z ? -1000000000.0f : s4.z * 0.125f;
            v[j * 4 + 3] = mk.w ? -1000000000.0f : s4.w * 0.125f;
#pragma unroll
            for (int u = 0; u < 4; u++) mx = fmaxf(mx, v[j * 4 + u]);
        }
#pragma unroll
        for (int o = 16; o; o >>= 1) mx = fmaxf(mx, __shfl_xor_sync(0xffffffffu, mx, o));
        float sum = 0.0f;
#pragma unroll
        for (int u = 0; u < 32; u++) { v[u] = fexp(v[u] - mx); sum += v[u]; }
#pragma unroll
        for (int o = 16; o; o >>= 1) sum += __shfl_xor_sync(0xffffffffu, sum, o);
        float iv = l0 / sum;
        const float* rrow = g_rel + ((size_t)b * Ss + q0 + row) * Ss;
        float* prow = probp + (bh * Ss + q0 + row) * Ss;
#pragma unroll
        for (int j = 0; j < 8; j++) {
            int col = lane * 4 + j * 128;
            float4 ra4 = *(const float4*)(rrow + col);
            float4 o;
            o.x = fmaf(v[j * 4 + 0], iv, l1 * ra4.x);
            o.y = fmaf(v[j * 4 + 1], iv, l1 * ra4.y);
            o.z = fmaf(v[j * 4 + 2], iv, l1 * ra4.z);
            o.w = fmaf(v[j * 4 + 3], iv, l1 * ra4.w);
            *(float4*)(prow + col) = o;
        }
    }
}

// ================= PV GEMM: out = P @ V ==================================
#define PV_SMEM (2 * 30720)
__global__ void __launch_bounds__(256, 1)
pv_mma(const float* __restrict__ probp, float* __restrict__ outp) {
    extern __shared__ char sm[];
    unsigned smb = smem_u32(sm);
    int tid = threadIdx.x, lane = tid & 31, wid = tid >> 5;
    int warp_m = wid >> 2, warp_n = wid & 3;
    int q0 = blockIdx.x * 128, bh = blockIdx.y;
    int b_ = bh / Hh, h_ = bh % Hh;

    float acc[4][2][4];
#pragma unroll
    for (int a = 0; a < 4; a++)
#pragma unroll
        for (int b = 0; b < 2; b++)
#pragma unroll
            for (int r = 0; r < 4; r++) acc[a][b][r] = 0.0f;

    const float* A0 = probp + ((size_t)bh * Ss + q0) * Ss;
    const float* B0 = g_Vt + (size_t)bh * HDd * Ss;
    R4<4> ra; R4<2> rb;
    gload<4>(A0, Ss, ra, tid);
    gload<2>(B0, Ss, rb, tid);
    cstore<4>(sm, sm + 10240, ra, tid);
    cstore<2>(sm + 20480, sm + 25600, rb, tid);
    __syncthreads();

    const int NC = Ss / 32;
    for (int cc = 0; cc < NC; cc++) {
        if (cc + 1 < NC) {
            gload<4>(A0 + (cc + 1) * 32, Ss, ra, tid);
            gload<2>(B0 + (cc + 1) * 32, Ss, rb, tid);
        }
        mma_chunk<2, 64>(acc, smb + (unsigned)(cc & 1) * 30720u, lane, warp_m, warp_n);
        if (cc + 1 < NC) {
            char* bn = sm + ((cc + 1) & 1) * 30720;
            cstore<4>(bn, bn + 10240, ra, tid);
            cstore<2>(bn + 20480, bn + 25600, rb, tid);
        }
        __syncthreads();
    }

#pragma unroll
    for (int ma = 0; ma < 4; ma++)
#pragma unroll
        for (int na = 0; na < 2; na++)
#pragma unroll
            for (int rp = 0; rp < 2; rp++) {
                int m = warp_m * 64 + ma * 16 + (lane >> 2) + rp * 8;
                int n0 = warp_n * 16 + na * 8 + (lane & 3) * 2;
                float2 v;
                v.x = acc[ma][na][rp * 2];
                v.y = acc[ma][na][rp * 2 + 1];
                *(float2*)(outp + ((size_t)b_ * Ss + q0 + m) * Dd + h_ * HDd + n0) = v;
            }
}

// ---------------- launcher ----------------------------------------------
extern "C" void kernel_launch(void* const* d_in, const int* in_sizes, int n_in,
                              void* d_out, int out_size) {
    const float* q   = (const float*)d_in[0];
    const float* k   = (const float*)d_in[1];
    const float* v   = (const float*)d_in[2];
    const float* rel = (const float*)d_in[3];
    const void*  msk = d_in[4];
    const float* l1  = (const float*)d_in[5];
    const float* Wq  = (const float*)d_in[6];
    const float* bq  = (const float*)d_in[7];
    const float* Wk  = (const float*)d_in[8];
    const float* bk  = (const float*)d_in[9];
    const float* Wv  = (const float*)d_in[10];
    const float* bv  = (const float*)d_in[11];

    float* outp = (float*)d_out;
    float* probp = outp + (size_t)Bb * Ss * Dd;

    cudaFuncSetAttribute(proj_mma,   cudaFuncAttributeMaxDynamicSharedMemorySize, PROJ_SMEM);
    cudaFuncSetAttribute(fused_attn, cudaFuncAttributeMaxDynamicSharedMemorySize, FA_SMEM);
    cudaFuncSetAttribute(pv_mma,     cudaFuncAttributeMaxDynamicSharedMemorySize, PV_SMEM);

    mask_detect_kernel<<<1, 256>>>(msk);
    mask_convert_kernel<<<(Bb * Ss * Ss) / 256, 256>>>(msk);

    rel_softmax_kernel<<<Bb * Ss, 256>>>(rel);

    dim3 gp(Dd / 128, (Bb * Ss) / 128, 3);
    proj_mma<<<gp, 256, PROJ_SMEM>>>(q, k, v, Wq, Wk, Wv, bq, bk, bv);

    dim3 gf(Ss / 32, Hh, Bb);
    fused_attn<<<gf, 256, FA_SMEM>>>(l1, probp);

    dim3 gv(Ss / 128, BH);
    pv_mma<<<gv, 256, PV_SMEM>>>(probp, outp);
}